// round 5
// baseline (speedup 1.0000x reference)
#include <cuda_runtime.h>
#include <math.h>

#define N_NODES 8192
#define N_EDGES 65536

typedef unsigned long long ull;

// ---------------- scratch (static device globals; no runtime alloc) ----------------
__device__ float g_S   [N_NODES*64];
__device__ float g_V   [N_NODES*192];
__device__ float g_EDN [N_EDGES];
__device__ float g_TP  [(size_t)N_EDGES*320];
__device__ float g_WM  [(size_t)N_EDGES*832];
__device__ float g_MS  [N_NODES*320];
__device__ float g_MV  [N_NODES*1536];
__device__ float g_AI  [N_NODES*10];          // attrs / (dens+1)
__device__ float g_MSP [N_NODES*64];
__device__ float g_MVP [N_NODES*192];
__device__ int   g_CNT [N_NODES];
__device__ int   g_CUR [N_NODES];
__device__ int   g_OFF [N_NODES+1];
__device__ int   g_SORT[N_EDGES];

__device__ __forceinline__ ull bcast(float f) {
    unsigned int u = __float_as_uint(f);
    ull r;
    asm("mov.b64 %0, {%1, %1};" : "=l"(r) : "r"(u));
    return r;
}
__device__ __forceinline__ void fma2(ull& acc, ull a, ull b) {
    asm("fma.rn.f32x2 %0, %1, %2, %0;" : "+l"(acc) : "l"(a), "l"(b));
}
__device__ __forceinline__ float lo2(ull v) { return __uint_as_float((unsigned int)v); }
__device__ __forceinline__ float hi2(ull v) { return __uint_as_float((unsigned int)(v >> 32)); }
__device__ __forceinline__ float silu(float v) { return v / (1.f + __expf(-v)); }

// ================= fused edge kernel =================
// Thread owns one edge. efm(16) and h(64) live in registers.
// Computes: WM = efm @ magw /4        (13 x 64-col tiles, K=16)
//           h  = 3-layer silu MLP     (K=16 then 64,64)
//           TP = h @ w3 /8            (5 x 64-col tiles, K=64)
__global__ void __launch_bounds__(128) k_edge(
    const float* __restrict__ EF, const float* __restrict__ MI,
    const int* __restrict__ EI,
    const float* __restrict__ w0, const float* __restrict__ w1,
    const float* __restrict__ w2, const float* __restrict__ w3,
    const float* __restrict__ magw)
{
    __shared__ float Bs[64*68];
    const int tid = threadIdx.x;
    const size_t e = (size_t)blockIdx.x * 128 + tid;

    float efm[16];
    {
        float4 a = *(const float4*)(EF + e * 8);
        float4 b = *(const float4*)(EF + e * 8 + 4);
        int snd = EI[e];
        float4 c = *(const float4*)(MI + (size_t)snd * 8);
        float4 d = *(const float4*)(MI + (size_t)snd * 8 + 4);
        efm[0]=a.x; efm[1]=a.y; efm[2]=a.z; efm[3]=a.w;
        efm[4]=b.x; efm[5]=b.y; efm[6]=b.z; efm[7]=b.w;
        efm[8]=c.x; efm[9]=c.y; efm[10]=c.z; efm[11]=c.w;
        efm[12]=d.x; efm[13]=d.y; efm[14]=d.z; efm[15]=d.w;
    }

    ull acc[32];

    // ---- magw projection: WM[e, j*64 + c] ----
    for (int j = 0; j < 13; j++) {
        __syncthreads();
        for (int i = tid; i < 16 * 16; i += 128) {
            int k = i >> 4, c4 = i & 15;
            *(float4*)(Bs + k * 68 + c4 * 4) =
                *(const float4*)(magw + (size_t)k * 832 + j * 64 + c4 * 4);
        }
        __syncthreads();
#pragma unroll
        for (int i = 0; i < 32; i++) acc[i] = 0ull;
#pragma unroll
        for (int k = 0; k < 16; k++) {
            ull a2 = bcast(efm[k]);
#pragma unroll
            for (int c4 = 0; c4 < 16; c4++) {
                ulonglong2 wv = *(const ulonglong2*)(Bs + k * 68 + c4 * 4);
                fma2(acc[2 * c4],     a2, wv.x);
                fma2(acc[2 * c4 + 1], a2, wv.y);
            }
        }
        float* dst = g_WM + e * 832 + j * 64;
#pragma unroll
        for (int i = 0; i < 16; i++) {
            float4 o;
            o.x = lo2(acc[2*i])   * 0.25f;  o.y = hi2(acc[2*i])   * 0.25f;
            o.z = lo2(acc[2*i+1]) * 0.25f;  o.w = hi2(acc[2*i+1]) * 0.25f;
            *(float4*)(dst + i * 4) = o;
        }
    }

    // ---- MLP layer 0: h = silu(efm @ w0 / 4) ----
    float h[64];
    {
        __syncthreads();
        for (int i = tid; i < 16 * 16; i += 128) {
            int k = i >> 4, c4 = i & 15;
            *(float4*)(Bs + k * 68 + c4 * 4) = *(const float4*)(w0 + k * 64 + c4 * 4);
        }
        __syncthreads();
#pragma unroll
        for (int i = 0; i < 32; i++) acc[i] = 0ull;
#pragma unroll
        for (int k = 0; k < 16; k++) {
            ull a2 = bcast(efm[k]);
#pragma unroll
            for (int c4 = 0; c4 < 16; c4++) {
                ulonglong2 wv = *(const ulonglong2*)(Bs + k * 68 + c4 * 4);
                fma2(acc[2 * c4],     a2, wv.x);
                fma2(acc[2 * c4 + 1], a2, wv.y);
            }
        }
#pragma unroll
        for (int i = 0; i < 32; i++) {
            h[2 * i]     = silu(lo2(acc[i]) * 0.25f);
            h[2 * i + 1] = silu(hi2(acc[i]) * 0.25f);
        }
    }

    // ---- MLP layers 1,2: h = silu(h @ w / 8) ----
    for (int l = 0; l < 2; l++) {
        const float* __restrict__ W = l ? w2 : w1;
        __syncthreads();
        for (int i = tid; i < 64 * 16; i += 128) {
            int k = i >> 4, c4 = i & 15;
            *(float4*)(Bs + k * 68 + c4 * 4) = *(const float4*)(W + k * 64 + c4 * 4);
        }
        __syncthreads();
#pragma unroll
        for (int i = 0; i < 32; i++) acc[i] = 0ull;
#pragma unroll
        for (int k = 0; k < 64; k++) {
            ull a2 = bcast(h[k]);
#pragma unroll
            for (int c4 = 0; c4 < 16; c4++) {
                ulonglong2 wv = *(const ulonglong2*)(Bs + k * 68 + c4 * 4);
                fma2(acc[2 * c4],     a2, wv.x);
                fma2(acc[2 * c4 + 1], a2, wv.y);
            }
        }
#pragma unroll
        for (int i = 0; i < 32; i++) {
            h[2 * i]     = silu(lo2(acc[i]) * 0.125f);
            h[2 * i + 1] = silu(hi2(acc[i]) * 0.125f);
        }
    }

    // ---- TP projection: TP[e, j*64 + c] = h @ w3 / 8 ----
    for (int j = 0; j < 5; j++) {
        __syncthreads();
        for (int i = tid; i < 64 * 16; i += 128) {
            int k = i >> 4, c4 = i & 15;
            *(float4*)(Bs + k * 68 + c4 * 4) =
                *(const float4*)(w3 + (size_t)k * 320 + j * 64 + c4 * 4);
        }
        __syncthreads();
#pragma unroll
        for (int i = 0; i < 32; i++) acc[i] = 0ull;
#pragma unroll
        for (int k = 0; k < 64; k++) {
            ull a2 = bcast(h[k]);
#pragma unroll
            for (int c4 = 0; c4 < 16; c4++) {
                ulonglong2 wv = *(const ulonglong2*)(Bs + k * 68 + c4 * 4);
                fma2(acc[2 * c4],     a2, wv.x);
                fma2(acc[2 * c4 + 1], a2, wv.y);
            }
        }
        float* dst = g_TP + e * 320 + j * 64;
#pragma unroll
        for (int i = 0; i < 16; i++) {
            float4 o;
            o.x = lo2(acc[2*i])   * 0.125f;  o.y = hi2(acc[2*i])   * 0.125f;
            o.z = lo2(acc[2*i+1]) * 0.125f;  o.w = hi2(acc[2*i+1]) * 0.125f;
            *(float4*)(dst + i * 4) = o;
        }
    }
}

// ================= register-blocked GEMM (node side) =================
template<int RB, bool SKIP>
__global__ void __launch_bounds__(128) gemmk(
    const float* __restrict__ A, long ars, int acs, long azs,
    const float* __restrict__ B0, const float* __restrict__ Bz, int brs,
    float* __restrict__ C, long crs, int ccs, long czs,
    int K, float alpha, int act,
    const float* __restrict__ MSP, const float* __restrict__ MVP)
{
    const int LDA = RB + 4;
    const int RPT = RB / 16;
    const int PPT = RPT / 2;
    __shared__ float As[32*(RB+4)];
    __shared__ float Bs[32*68];

    const int tid = threadIdx.x;
    const int tx = tid & 7;
    const int ty = tid >> 3;
    const long row0 = (long)blockIdx.x * RB;
    const int  col0 = blockIdx.y * 64;
    const int  z = blockIdx.z;
    const float* __restrict__ B = (z == 0) ? B0 : Bz;
    C += (long)z * czs;

    const int arow = tid & (RB - 1);
    const int kseg = (RB == 128) ? 0 : ((tid >> 6) * 16);
    const int KPT  = (RB == 128) ? 32 : 16;

    const float* Arow;
    const float* ai = 0;
    if (SKIP) {
        Arow = (z == 0) ? (MSP + (row0 + arow) * 64)
                        : (MVP + (row0 + arow) * 192 + (z - 1) * 64);
        ai = g_AI + (row0 + arow) * 10;
    } else {
        Arow = A + (long)z * azs + (row0 + arow) * ars;
    }

    ull acc[PPT * 8];
#pragma unroll
    for (int i = 0; i < PPT * 8; i++) acc[i] = 0ull;

    for (int k0 = 0; k0 < K; k0 += 32) {
        if (SKIP) {
#pragma unroll 8
            for (int c = 0; c < KPT; c++) {
                int k = k0 + kseg + c;
                int u = (k * 6554) >> 16;
                int v = k - u * 10;
                As[(kseg + c) * LDA + arow] = Arow[u] * ai[v];
            }
        } else if (acs == 1) {
#pragma unroll
            for (int c = 0; c < KPT / 4; c++) {
                int kk = kseg + c * 4;
                float4 val = make_float4(0.f, 0.f, 0.f, 0.f);
                if (k0 + kk < K)
                    val = *(const float4*)(Arow + k0 + kk);
                As[(kk + 0) * LDA + arow] = val.x;
                As[(kk + 1) * LDA + arow] = val.y;
                As[(kk + 2) * LDA + arow] = val.z;
                As[(kk + 3) * LDA + arow] = val.w;
            }
        } else {
#pragma unroll 8
            for (int c = 0; c < KPT; c++) {
                int kk = kseg + c;
                float v = 0.f;
                if (k0 + kk < K) v = Arow[(long)(k0 + kk) * acs];
                As[kk * LDA + arow] = v;
            }
        }
#pragma unroll
        for (int j = 0; j < 4; j++) {
            int kk = (tid >> 4) + j * 8;
            int c  = (tid & 15) * 4;
            float4 val = make_float4(0.f, 0.f, 0.f, 0.f);
            if (k0 + kk < K)
                val = *(const float4*)(B + (size_t)(k0 + kk) * brs + col0 + c);
            *(float4*)(Bs + kk * 68 + c) = val;
        }
        __syncthreads();

#pragma unroll 4
        for (int kk = 0; kk < 32; kk++) {
            ull ar[PPT];
            {
                const ulonglong2* ap = (const ulonglong2*)(As + kk * LDA + ty * RPT);
                ulonglong2 t0 = ap[0];
                ar[0] = t0.x; ar[1] = t0.y;
                if (RB == 128) {
                    ulonglong2 t1 = ap[1];
                    ar[2] = t1.x; ar[3] = t1.y;
                }
            }
            const float4* bp = (const float4*)(Bs + kk * 68 + tx * 8);
            float4 b0 = bp[0], b1 = bp[1];
            ull bb[8];
            bb[0] = bcast(b0.x); bb[1] = bcast(b0.y);
            bb[2] = bcast(b0.z); bb[3] = bcast(b0.w);
            bb[4] = bcast(b1.x); bb[5] = bcast(b1.y);
            bb[6] = bcast(b1.z); bb[7] = bcast(b1.w);
#pragma unroll
            for (int c = 0; c < 8; c++)
#pragma unroll
                for (int p = 0; p < PPT; p++)
                    fma2(acc[p * 8 + c], ar[p], bb[c]);
        }
        __syncthreads();
    }

#pragma unroll
    for (int rp = 0; rp < PPT; rp++) {
        long r = row0 + ty * RPT + rp * 2;
        float lo[8], hi[8];
#pragma unroll
        for (int c = 0; c < 8; c++) {
            ull av = acc[rp * 8 + c];
            float v0 = lo2(av) * alpha;
            float v1 = hi2(av) * alpha;
            if (act) { v0 = silu(v0); v1 = silu(v1); }
            lo[c] = v0; hi[c] = v1;
        }
        if (ccs == 1) {
            float* c0 = C + r * crs + col0 + tx * 8;
            float* c1 = c0 + crs;
            *(float4*)(c0)     = make_float4(lo[0], lo[1], lo[2], lo[3]);
            *(float4*)(c0 + 4) = make_float4(lo[4], lo[5], lo[6], lo[7]);
            *(float4*)(c1)     = make_float4(hi[0], hi[1], hi[2], hi[3]);
            *(float4*)(c1 + 4) = make_float4(hi[4], hi[5], hi[6], hi[7]);
        } else {
#pragma unroll
            for (int c = 0; c < 8; c++) {
                long col = (long)(col0 + tx * 8 + c) * ccs;
                C[r * crs + col] = lo[c];
                C[(r + 1) * crs + col] = hi[c];
            }
        }
    }
}

// ---------------- counting sort by receiver (hist fused with density) ----------------
__global__ void k_zero()
{
    int i = blockIdx.x * 256 + threadIdx.x;
    if (i < N_NODES) { g_CNT[i] = 0; g_CUR[i] = 0; }
}
__global__ void k_hist(const int* __restrict__ EI, const float* __restrict__ EF,
                       const float* __restrict__ DW)
{
    int e = blockIdx.x * 256 + threadIdx.x;
    atomicAdd(&g_CNT[EI[N_EDGES + e]], 1);
    float d = 0.f;
#pragma unroll
    for (int i = 0; i < 8; i++) d += EF[e * 8 + i] * DW[i];
    d *= 0.3535533905932738f;                     // 1/sqrt(8)
    g_EDN[e] = tanhf(d * d);
}
__global__ void k_scan()
{
    __shared__ int part[1024];
    int t = threadIdx.x;
    int loc[8]; int s = 0;
#pragma unroll
    for (int j = 0; j < 8; j++) { loc[j] = s; s += g_CNT[t * 8 + j]; }
    part[t] = s;
    __syncthreads();
    for (int off = 1; off < 1024; off <<= 1) {
        int v = (t >= off) ? part[t - off] : 0;
        __syncthreads();
        part[t] += v;
        __syncthreads();
    }
    int excl = part[t] - s;
#pragma unroll
    for (int j = 0; j < 8; j++) g_OFF[t * 8 + j] = excl + loc[j];
    if (t == 1023) g_OFF[N_NODES] = part[1023];
}
__global__ void k_scatter(const int* __restrict__ EI)
{
    int e = blockIdx.x * 256 + threadIdx.x;
    int r = EI[N_EDGES + e];
    int p = g_OFF[r] + atomicAdd(&g_CUR[r], 1);
    g_SORT[p] = e;
}

// ---------------- per-node edge combine + segment reduction (no atomics) ----------------
__global__ void __launch_bounds__(64) k_mm(const float* __restrict__ EA,
                                           const float* __restrict__ MA,
                                           const int* __restrict__ EI,
                                           const float* __restrict__ ATTR)
{
    const int n = blockIdx.x;
    const int u = threadIdx.x;
    const int beg = g_OFF[n], end = g_OFF[n + 1];

    float as0 = 0, as1 = 0, as2 = 0, as3 = 0, as4 = 0;
    float av[8][3];
#pragma unroll
    for (int j = 0; j < 8; j++)
#pragma unroll
        for (int i = 0; i < 3; i++) av[j][i] = 0.f;
    float dens = 0.f;

    const float I3 = 0.5773502691896258f;   // 1/sqrt(3)
    const float I2 = 0.7071067811865476f;   // 1/sqrt(2)

    int e_nx = 0, s_nx = 0;
    if (beg < end) { e_nx = g_SORT[beg]; s_nx = EI[e_nx]; }

    for (int q = beg; q < end; q++) {
        const int e = e_nx, snd = s_nx;
        if (q + 1 < end) { e_nx = g_SORT[q + 1]; s_nx = EI[e_nx]; }

        const float4 eav = *(const float4*)(EA + (size_t)e * 4);
        const float y0 = eav.x, yx = eav.y, yy = eav.z, yz = eav.w;
        const float4 mav = *(const float4*)(MA + (size_t)snd * 4);
        const float m0 = mav.x, mx = mav.y, my = mav.z, mz = mav.w;
        const float xs = g_S[(size_t)snd * 64 + u];
        const float* vp = g_V + (size_t)snd * 192 + u;
        const float vx = vp[0], vy = vp[64], vz = vp[128];
        const float* tp = g_TP + (size_t)e * 320 + u;
        const float t0 = tp[0], t1 = tp[64], t2 = tp[128], t3 = tp[192], t4 = tp[256];
        const float* wm = g_WM + (size_t)e * 832 + u;

        const float ms0 = t0 * xs * y0;
        const float A0x = t1 * xs * yx, A0y = t1 * xs * yy, A0z = t1 * xs * yz;
        const float B0x = t2 * vx * y0, B0y = t2 * vy * y0, B0z = t2 * vz * y0;
        const float ms1 = t3 * (vx * yx + vy * yy + vz * yz) * I3;
        const float cx = vy * yz - vz * yy;
        const float cy = vz * yx - vx * yz;
        const float cz = vx * yy - vy * yx;
        const float C0x = t4 * cx * I2, C0y = t4 * cy * I2, C0z = t4 * cz * I2;

        as0 += wm[0] * ms0 * m0;
        { float w_ = wm[64] * ms0;  av[0][0] += w_ * mx; av[0][1] += w_ * my; av[0][2] += w_ * mz; }
        as1 += wm[128] * ms1 * m0;
        { float w_ = wm[192] * ms1; av[1][0] += w_ * mx; av[1][1] += w_ * my; av[1][2] += w_ * mz; }

        { float w_ = wm[256] * m0;  av[2][0] += w_ * A0x; av[2][1] += w_ * A0y; av[2][2] += w_ * A0z; }
        as2 += wm[320] * (A0x * mx + A0y * my + A0z * mz) * I3;
        { float w_ = wm[384] * I2;
          av[3][0] += w_ * (A0y * mz - A0z * my);
          av[3][1] += w_ * (A0z * mx - A0x * mz);
          av[3][2] += w_ * (A0x * my - A0y * mx); }

        { float w_ = wm[448] * m0;  av[4][0] += w_ * B0x; av[4][1] += w_ * B0y; av[4][2] += w_ * B0z; }
        as3 += wm[512] * (B0x * mx + B0y * my + B0z * mz) * I3;
        { float w_ = wm[576] * I2;
          av[5][0] += w_ * (B0y * mz - B0z * my);
          av[5][1] += w_ * (B0z * mx - B0x * mz);
          av[5][2] += w_ * (B0x * my - B0y * mx); }

        { float w_ = wm[640] * m0;  av[6][0] += w_ * C0x; av[6][1] += w_ * C0y; av[6][2] += w_ * C0z; }
        as4 += wm[704] * (C0x * mx + C0y * my + C0z * mz) * I3;
        { float w_ = wm[768] * I2;
          av[7][0] += w_ * (C0y * mz - C0z * my);
          av[7][1] += w_ * (C0z * mx - C0x * mz);
          av[7][2] += w_ * (C0x * my - C0y * mx); }

        dens += g_EDN[e];
    }

    const size_t b = (size_t)n * 320 + u;
    g_MS[b]       = as0;
    g_MS[b + 64]  = as1;
    g_MS[b + 128] = as2;
    g_MS[b + 192] = as3;
    g_MS[b + 256] = as4;
    const size_t bv = (size_t)n * 1536 + u;
#pragma unroll
    for (int i = 0; i < 3; i++)
#pragma unroll
        for (int j = 0; j < 8; j++)
            g_MV[bv + i * 512 + j * 64] = av[j][i];
    if (u < 10) g_AI[n * 10 + u] = ATTR[n * 10 + u] / (dens + 1.f);
}

// ---------------- launcher ----------------
extern "C" void kernel_launch(void* const* d_in, const int* in_sizes, int n_in,
                              void* d_out, int out_size)
{
    (void)in_sizes; (void)n_in; (void)out_size;
    const float* node_attrs = (const float*)d_in[0];
    const float* node_feats = (const float*)d_in[1];
    const float* edge_attrs = (const float*)d_in[2];
    const float* edge_feats = (const float*)d_in[3];
    const int*   edge_index = (const int*)  d_in[4];
    const float* maginv     = (const float*)d_in[5];
    const float* magattr    = (const float*)d_in[6];
    const float* Wups       = (const float*)d_in[7];
    const float* Wupv       = (const float*)d_in[8];
    const float* w0         = (const float*)d_in[9];
    const float* w1         = (const float*)d_in[10];
    const float* w2         = (const float*)d_in[11];
    const float* w3         = (const float*)d_in[12];
    const float* magw       = (const float*)d_in[13];
    const float* densw      = (const float*)d_in[14];
    const float* lins       = (const float*)d_in[15];
    const float* linv       = (const float*)d_in[16];
    const float* skips      = (const float*)d_in[17];
    const float* skipv      = (const float*)d_in[18];
    float* out = (float*)d_out;

    float *pS, *pV, *pMS, *pMV, *pMSP, *pMVP;
    cudaGetSymbolAddress((void**)&pS,   g_S);
    cudaGetSymbolAddress((void**)&pV,   g_V);
    cudaGetSymbolAddress((void**)&pMS,  g_MS);
    cudaGetSymbolAddress((void**)&pMV,  g_MV);
    cudaGetSymbolAddress((void**)&pMSP, g_MSP);
    cudaGetSymbolAddress((void**)&pMVP, g_MVP);

    const float a8   = 0.125f;
    const float a320 = 1.f / sqrtf(320.f);
    const float a512 = 1.f / sqrtf(512.f);
    const float a640 = 1.f / sqrtf(640.f);

    // sort bookkeeping first so k_edge lands in profile slot 3
    k_zero   <<<N_NODES/256, 256>>>();                                   // 0
    k_hist   <<<N_EDGES/256, 256>>>(edge_index, edge_feats, densw);      // 1
    k_scan   <<<1, 1024>>>();                                            // 2

    // fused edge path: WM + MLP + TP in one kernel                      // 3 (profiled)
    k_edge<<<N_EDGES/128, 128>>>(edge_feats, maginv, edge_index,
                                 w0, w1, w2, w3, magw);

    k_scatter<<<N_EDGES/256, 256>>>(edge_index);                         // 4

    // node up-projection
    gemmk<64,false><<<dim3(N_NODES/64, 1, 1), 128>>>(node_feats, 256, 1, 0, Wups, Wups, 64,
                                                     pS, 64, 1, 0, 64, a8, 0, 0, 0);
    gemmk<64,false><<<dim3(N_NODES/64, 1, 3), 128>>>(node_feats + 64, 256, 3, 1, Wupv, Wupv, 64,
                                                     pV, 192, 1, 64, 64, a8, 0, 0, 0);

    // per-node tensor-product combine + segment reduction (+ g_AI)
    k_mm<<<N_NODES, 64>>>(edge_attrs, magattr, edge_index, node_attrs);

    // lin_s / lin_v
    gemmk<64,false><<<dim3(N_NODES/64, 1, 1), 128>>>(pMS, 320, 1, 0, lins, lins, 64,
                                                     pMSP, 64, 1, 0, 320, a320, 0, 0, 0);
    gemmk<64,false><<<dim3(N_NODES/64, 1, 3), 128>>>(pMV, 1536, 1, 512, linv, linv, 64,
                                                     pMVP, 192, 1, 64, 512, a512, 0, 0, 0);

    // skip einsum: coefficients built on the fly in A-staging
    gemmk<128,true><<<dim3(N_NODES/128, 1, 4), 128>>>(0, 0, 0, 0, skips, skipv, 64,
                                                      out, 256, 4, 1, 640, a640, 0, pMSP, pMVP);
}

// round 6
// speedup vs baseline: 1.2187x; 1.2187x over previous
#include <cuda_runtime.h>
#include <math.h>

#define N_NODES 8192
#define N_EDGES 65536

typedef unsigned long long ull;

// ---------------- scratch (static device globals; no runtime alloc) ----------------
__device__ float g_S   [N_NODES*64];
__device__ float g_V   [N_NODES*192];
__device__ float g_EFM [(size_t)N_EDGES*16];
__device__ float g_EDN [N_EDGES];
__device__ float g_HA  [(size_t)N_EDGES*64];
__device__ float g_HB  [(size_t)N_EDGES*64];
__device__ float g_TP  [(size_t)N_EDGES*320];
__device__ float g_WM  [(size_t)N_EDGES*832];
__device__ float g_MS  [N_NODES*320];
__device__ float g_MV  [N_NODES*1536];
__device__ float g_AI  [N_NODES*10];          // attrs / (dens+1)
__device__ float g_MSP [N_NODES*64];
__device__ float g_MVP [N_NODES*192];
__device__ int   g_CNT [N_NODES];
__device__ int   g_CUR [N_NODES];
__device__ int   g_OFF [N_NODES+1];
__device__ int   g_SORT[N_EDGES];

__device__ __forceinline__ ull bcast(float f) {
    unsigned int u = __float_as_uint(f);
    ull r;
    asm("mov.b64 %0, {%1, %1};" : "=l"(r) : "r"(u));
    return r;
}
__device__ __forceinline__ void fma2(ull& acc, ull a, ull b) {
    asm("fma.rn.f32x2 %0, %1, %2, %0;" : "+l"(acc) : "l"(a), "l"(b));
}
__device__ __forceinline__ float lo2(ull v) { return __uint_as_float((unsigned int)v); }
__device__ __forceinline__ float hi2(ull v) { return __uint_as_float((unsigned int)(v >> 32)); }
__device__ __forceinline__ float silu(float v) { return v / (1.f + __expf(-v)); }

// ================= register-blocked GEMM =================
// Tile: RB rows x 64 cols per block, 128 threads, k-tile KT (16 or 32).
// RB=128: 8x8 microtile; RB=64: 4x8 microtile. Rows paired in f32x2.
// C[row, col, z] = act( alpha * sum_k A[z][row,k] * B[z][k,col] )
// Normal mode:  A element (n,k) = (A + z*azs)[n*ars + k*acs]
// SKIP mode:    A(n,k) = msel[n, k/10] * g_AI[n*10 + k%10],
//   msel = (z==0 ? MSP stride 64 : MVP + (z-1)*64, stride 192)
// B: z==0 -> B0, else Bz;  B[k*brs + col]
// C: (C + z*czs)[row*crs + col*ccs]
template<int RB, int KT, bool SKIP>
__global__ void __launch_bounds__(128) gemmk(
    const float* __restrict__ A, long ars, int acs, long azs,
    const float* __restrict__ B0, const float* __restrict__ Bz, int brs,
    float* __restrict__ C, long crs, int ccs, long czs,
    int K, float alpha, int act,
    const float* __restrict__ MSP, const float* __restrict__ MVP)
{
    const int LDA = RB + 4;
    const int RPT = RB / 16;       // rows per thread (8 or 4)
    const int PPT = RPT / 2;       // row pairs per thread
    __shared__ float As[KT*(RB+4)];
    __shared__ float Bs[KT*68];

    const int tid = threadIdx.x;
    const int tx = tid & 7;
    const int ty = tid >> 3;
    const long row0 = (long)blockIdx.x * RB;
    const int  col0 = blockIdx.y * 64;
    const int  z = blockIdx.z;
    const float* __restrict__ B = (z == 0) ? B0 : Bz;
    C += (long)z * czs;

    // A staging ownership: thread owns row (tid % RB), k-segment (tid/RB)*(KT/2)
    const int arow = tid & (RB - 1);
    const int kseg = (RB == 128) ? 0 : ((tid >> 6) * (KT / 2));
    const int KPT  = (RB == 128) ? KT : KT / 2;

    const float* Arow;
    const float* ai = 0;
    if (SKIP) {
        Arow = (z == 0) ? (MSP + (row0 + arow) * 64)
                        : (MVP + (row0 + arow) * 192 + (z - 1) * 64);
        ai = g_AI + (row0 + arow) * 10;
    } else {
        Arow = A + (long)z * azs + (row0 + arow) * ars;
    }

    ull acc[PPT * 8];
#pragma unroll
    for (int i = 0; i < PPT * 8; i++) acc[i] = 0ull;

    for (int k0 = 0; k0 < K; k0 += KT) {
        // ---- stage A ----
        if (SKIP) {
#pragma unroll 8
            for (int c = 0; c < KPT; c++) {
                int k = k0 + kseg + c;            // K=640 exact -> no guard
                int u = (k * 6554) >> 16;
                int v = k - u * 10;
                As[(kseg + c) * LDA + arow] = Arow[u] * ai[v];
            }
        } else if (acs == 1) {
#pragma unroll
            for (int c = 0; c < KPT / 4; c++) {
                int kk = kseg + c * 4;
                float4 val = make_float4(0.f, 0.f, 0.f, 0.f);
                if (k0 + kk < K)
                    val = *(const float4*)(Arow + k0 + kk);
                As[(kk + 0) * LDA + arow] = val.x;
                As[(kk + 1) * LDA + arow] = val.y;
                As[(kk + 2) * LDA + arow] = val.z;
                As[(kk + 3) * LDA + arow] = val.w;
            }
        } else {
#pragma unroll 8
            for (int c = 0; c < KPT; c++) {
                int kk = kseg + c;
                float v = 0.f;
                if (k0 + kk < K) v = Arow[(long)(k0 + kk) * acs];
                As[kk * LDA + arow] = v;
            }
        }
        // ---- stage B ----
#pragma unroll
        for (int j = 0; j < KT / 8; j++) {
            int kk = (tid >> 4) + j * 8;
            int c  = (tid & 15) * 4;
            float4 val = make_float4(0.f, 0.f, 0.f, 0.f);
            if (k0 + kk < K)
                val = *(const float4*)(B + (size_t)(k0 + kk) * brs + col0 + c);
            *(float4*)(Bs + kk * 68 + c) = val;
        }
        __syncthreads();

#pragma unroll 4
        for (int kk = 0; kk < KT; kk++) {
            ull ar[PPT];
            {
                const ulonglong2* ap = (const ulonglong2*)(As + kk * LDA + ty * RPT);
                ulonglong2 t0 = ap[0];
                ar[0] = t0.x; ar[1] = t0.y;
                if (RB == 128) {
                    ulonglong2 t1 = ap[1];
                    ar[2] = t1.x; ar[3] = t1.y;
                }
            }
            const float4* bp = (const float4*)(Bs + kk * 68 + tx * 8);
            float4 b0 = bp[0], b1 = bp[1];
            ull bb[8];
            bb[0] = bcast(b0.x); bb[1] = bcast(b0.y);
            bb[2] = bcast(b0.z); bb[3] = bcast(b0.w);
            bb[4] = bcast(b1.x); bb[5] = bcast(b1.y);
            bb[6] = bcast(b1.z); bb[7] = bcast(b1.w);
#pragma unroll
            for (int c = 0; c < 8; c++)
#pragma unroll
                for (int p = 0; p < PPT; p++)
                    fma2(acc[p * 8 + c], ar[p], bb[c]);
        }
        __syncthreads();
    }

    // ---- epilogue ----
#pragma unroll
    for (int rp = 0; rp < PPT; rp++) {
        long r = row0 + ty * RPT + rp * 2;
        float lo[8], hi[8];
#pragma unroll
        for (int c = 0; c < 8; c++) {
            ull av = acc[rp * 8 + c];
            float v0 = lo2(av) * alpha;
            float v1 = hi2(av) * alpha;
            if (act) { v0 = silu(v0); v1 = silu(v1); }
            lo[c] = v0; hi[c] = v1;
        }
        if (ccs == 1) {
            float* c0 = C + r * crs + col0 + tx * 8;
            float* c1 = c0 + crs;
            *(float4*)(c0)     = make_float4(lo[0], lo[1], lo[2], lo[3]);
            *(float4*)(c0 + 4) = make_float4(lo[4], lo[5], lo[6], lo[7]);
            *(float4*)(c1)     = make_float4(hi[0], hi[1], hi[2], hi[3]);
            *(float4*)(c1 + 4) = make_float4(hi[4], hi[5], hi[6], hi[7]);
        } else {
#pragma unroll
            for (int c = 0; c < 8; c++) {
                long col = (long)(col0 + tx * 8 + c) * ccs;
                C[r * crs + col] = lo[c];
                C[(r + 1) * crs + col] = hi[c];
            }
        }
    }
}

// ---------------- efm build ----------------
__global__ void k_efm(const float* __restrict__ EF, const float* __restrict__ MI,
                      const int* __restrict__ EI)
{
    int idx = blockIdx.x * 256 + threadIdx.x;     // E*16 threads
    int e = idx >> 4, k = idx & 15;
    float v;
    if (k < 8) v = EF[e * 8 + k];
    else       v = MI[(size_t)EI[e] * 8 + (k - 8)];
    g_EFM[idx] = v;
}

// ---------------- counting sort by receiver (hist fused with density) ----------------
__global__ void k_zero()
{
    int i = blockIdx.x * 256 + threadIdx.x;
    if (i < N_NODES) { g_CNT[i] = 0; g_CUR[i] = 0; }
}
__global__ void k_hist(const int* __restrict__ EI, const float* __restrict__ EF,
                       const float* __restrict__ DW)
{
    int e = blockIdx.x * 256 + threadIdx.x;
    atomicAdd(&g_CNT[EI[N_EDGES + e]], 1);
    float d = 0.f;
#pragma unroll
    for (int i = 0; i < 8; i++) d += EF[e * 8 + i] * DW[i];
    d *= 0.3535533905932738f;                     // 1/sqrt(8)
    g_EDN[e] = tanhf(d * d);
}
__global__ void k_scan()
{
    __shared__ int part[1024];
    int t = threadIdx.x;
    int loc[8]; int s = 0;
#pragma unroll
    for (int j = 0; j < 8; j++) { loc[j] = s; s += g_CNT[t * 8 + j]; }
    part[t] = s;
    __syncthreads();
    for (int off = 1; off < 1024; off <<= 1) {
        int v = (t >= off) ? part[t - off] : 0;
        __syncthreads();
        part[t] += v;
        __syncthreads();
    }
    int excl = part[t] - s;
#pragma unroll
    for (int j = 0; j < 8; j++) g_OFF[t * 8 + j] = excl + loc[j];
    if (t == 1023) g_OFF[N_NODES] = part[1023];
}
__global__ void k_scatter(const int* __restrict__ EI)
{
    int e = blockIdx.x * 256 + threadIdx.x;
    int r = EI[N_EDGES + e];
    int p = g_OFF[r] + atomicAdd(&g_CUR[r], 1);
    g_SORT[p] = e;
}

// ---------------- per-node edge combine + segment reduction (no atomics) ----------------
__global__ void __launch_bounds__(64) k_mm(const float* __restrict__ EA,
                                           const float* __restrict__ MA,
                                           const int* __restrict__ EI,
                                           const float* __restrict__ ATTR)
{
    const int n = blockIdx.x;
    const int u = threadIdx.x;
    const int beg = g_OFF[n], end = g_OFF[n + 1];

    float as0 = 0, as1 = 0, as2 = 0, as3 = 0, as4 = 0;
    float av[8][3];
#pragma unroll
    for (int j = 0; j < 8; j++)
#pragma unroll
        for (int i = 0; i < 3; i++) av[j][i] = 0.f;
    float dens = 0.f;

    const float I3 = 0.5773502691896258f;   // 1/sqrt(3)
    const float I2 = 0.7071067811865476f;   // 1/sqrt(2)

    int e_nx = 0, s_nx = 0;
    if (beg < end) { e_nx = g_SORT[beg]; s_nx = EI[e_nx]; }

    for (int q = beg; q < end; q++) {
        const int e = e_nx, snd = s_nx;
        if (q + 1 < end) { e_nx = g_SORT[q + 1]; s_nx = EI[e_nx]; }

        const float4 eav = *(const float4*)(EA + (size_t)e * 4);
        const float y0 = eav.x, yx = eav.y, yy = eav.z, yz = eav.w;
        const float4 mav = *(const float4*)(MA + (size_t)snd * 4);
        const float m0 = mav.x, mx = mav.y, my = mav.z, mz = mav.w;
        const float xs = g_S[(size_t)snd * 64 + u];
        const float* vp = g_V + (size_t)snd * 192 + u;
        const float vx = vp[0], vy = vp[64], vz = vp[128];
        const float* tp = g_TP + (size_t)e * 320 + u;
        const float t0 = tp[0], t1 = tp[64], t2 = tp[128], t3 = tp[192], t4 = tp[256];
        const float* wm = g_WM + (size_t)e * 832 + u;

        const float ms0 = t0 * xs * y0;
        const float A0x = t1 * xs * yx, A0y = t1 * xs * yy, A0z = t1 * xs * yz;
        const float B0x = t2 * vx * y0, B0y = t2 * vy * y0, B0z = t2 * vz * y0;
        const float ms1 = t3 * (vx * yx + vy * yy + vz * yz) * I3;
        const float cx = vy * yz - vz * yy;
        const float cy = vz * yx - vx * yz;
        const float cz = vx * yy - vy * yx;
        const float C0x = t4 * cx * I2, C0y = t4 * cy * I2, C0z = t4 * cz * I2;

        as0 += wm[0] * ms0 * m0;
        { float w_ = wm[64] * ms0;  av[0][0] += w_ * mx; av[0][1] += w_ * my; av[0][2] += w_ * mz; }
        as1 += wm[128] * ms1 * m0;
        { float w_ = wm[192] * ms1; av[1][0] += w_ * mx; av[1][1] += w_ * my; av[1][2] += w_ * mz; }

        { float w_ = wm[256] * m0;  av[2][0] += w_ * A0x; av[2][1] += w_ * A0y; av[2][2] += w_ * A0z; }
        as2 += wm[320] * (A0x * mx + A0y * my + A0z * mz) * I3;
        { float w_ = wm[384] * I2;
          av[3][0] += w_ * (A0y * mz - A0z * my);
          av[3][1] += w_ * (A0z * mx - A0x * mz);
          av[3][2] += w_ * (A0x * my - A0y * mx); }

        { float w_ = wm[448] * m0;  av[4][0] += w_ * B0x; av[4][1] += w_ * B0y; av[4][2] += w_ * B0z; }
        as3 += wm[512] * (B0x * mx + B0y * my + B0z * mz) * I3;
        { float w_ = wm[576] * I2;
          av[5][0] += w_ * (B0y * mz - B0z * my);
          av[5][1] += w_ * (B0z * mx - B0x * mz);
          av[5][2] += w_ * (B0x * my - B0y * mx); }

        { float w_ = wm[640] * m0;  av[6][0] += w_ * C0x; av[6][1] += w_ * C0y; av[6][2] += w_ * C0z; }
        as4 += wm[704] * (C0x * mx + C0y * my + C0z * mz) * I3;
        { float w_ = wm[768] * I2;
          av[7][0] += w_ * (C0y * mz - C0z * my);
          av[7][1] += w_ * (C0z * mx - C0x * mz);
          av[7][2] += w_ * (C0x * my - C0y * mx); }

        dens += g_EDN[e];
    }

    const size_t b = (size_t)n * 320 + u;
    g_MS[b]       = as0;
    g_MS[b + 64]  = as1;
    g_MS[b + 128] = as2;
    g_MS[b + 192] = as3;
    g_MS[b + 256] = as4;
    const size_t bv = (size_t)n * 1536 + u;
#pragma unroll
    for (int i = 0; i < 3; i++)
#pragma unroll
        for (int j = 0; j < 8; j++)
            g_MV[bv + i * 512 + j * 64] = av[j][i];
    if (u < 10) g_AI[n * 10 + u] = ATTR[n * 10 + u] / (dens + 1.f);
}

// ---------------- launcher ----------------
extern "C" void kernel_launch(void* const* d_in, const int* in_sizes, int n_in,
                              void* d_out, int out_size)
{
    (void)in_sizes; (void)n_in; (void)out_size;
    const float* node_attrs = (const float*)d_in[0];
    const float* node_feats = (const float*)d_in[1];
    const float* edge_attrs = (const float*)d_in[2];
    const float* edge_feats = (const float*)d_in[3];
    const int*   edge_index = (const int*)  d_in[4];
    const float* maginv     = (const float*)d_in[5];
    const float* magattr    = (const float*)d_in[6];
    const float* Wups       = (const float*)d_in[7];
    const float* Wupv       = (const float*)d_in[8];
    const float* w0         = (const float*)d_in[9];
    const float* w1         = (const float*)d_in[10];
    const float* w2         = (const float*)d_in[11];
    const float* w3         = (const float*)d_in[12];
    const float* magw       = (const float*)d_in[13];
    const float* densw      = (const float*)d_in[14];
    const float* lins       = (const float*)d_in[15];
    const float* linv       = (const float*)d_in[16];
    const float* skips      = (const float*)d_in[17];
    const float* skipv      = (const float*)d_in[18];
    float* out = (float*)d_out;

    float *pS, *pV, *pEFM, *pHA, *pHB, *pTP, *pWM, *pMS, *pMV, *pMSP, *pMVP;
    cudaGetSymbolAddress((void**)&pS,   g_S);
    cudaGetSymbolAddress((void**)&pV,   g_V);
    cudaGetSymbolAddress((void**)&pEFM, g_EFM);
    cudaGetSymbolAddress((void**)&pHA,  g_HA);
    cudaGetSymbolAddress((void**)&pHB,  g_HB);
    cudaGetSymbolAddress((void**)&pTP,  g_TP);
    cudaGetSymbolAddress((void**)&pWM,  g_WM);
    cudaGetSymbolAddress((void**)&pMS,  g_MS);
    cudaGetSymbolAddress((void**)&pMV,  g_MV);
    cudaGetSymbolAddress((void**)&pMSP, g_MSP);
    cudaGetSymbolAddress((void**)&pMVP, g_MVP);

    const float a8   = 0.125f;                  // 1/sqrt(64)
    const float a4   = 0.25f;                   // 1/sqrt(16)
    const float a320 = 1.f / sqrtf(320.f);
    const float a512 = 1.f / sqrtf(512.f);
    const float a640 = 1.f / sqrtf(640.f);      // 1/fan

    const int EB = N_EDGES / 128;   // 512

    // --- edge path first (slot 3 = magw GEMM with KT=16 fix, for ncu) ---
    k_efm<<<N_EDGES*16/256, 256>>>(edge_feats, maginv, edge_index);                           // 0
    gemmk<128,16,false><<<dim3(EB, 1,  1), 128>>>(pEFM, 16, 1, 0, w0, w0, 64,
                                                  pHA, 64, 1, 0, 16, a4, 1, 0, 0);           // 1
    gemmk<128,32,false><<<dim3(EB, 1,  1), 128>>>(pHA, 64, 1, 0, w1, w1, 64,
                                                  pHB, 64, 1, 0, 64, a8, 1, 0, 0);           // 2
    gemmk<128,16,false><<<dim3(EB, 13, 1), 128>>>(pEFM, 16, 1, 0, magw, magw, 832,
                                                  pWM, 832, 1, 0, 16, a4, 0, 0, 0);          // 3 (profiled)
    gemmk<128,32,false><<<dim3(EB, 1,  1), 128>>>(pHB, 64, 1, 0, w2, w2, 64,
                                                  pHA, 64, 1, 0, 64, a8, 1, 0, 0);           // 4
    gemmk<128,32,false><<<dim3(EB, 5,  1), 128>>>(pHA, 64, 1, 0, w3, w3, 320,
                                                  pTP, 320, 1, 0, 64, a8, 0, 0, 0);          // 5

    // node up-projection (RB=64)
    gemmk<64,32,false><<<dim3(N_NODES/64, 1, 1), 128>>>(node_feats, 256, 1, 0, Wups, Wups, 64,
                                                        pS, 64, 1, 0, 64, a8, 0, 0, 0);
    gemmk<64,32,false><<<dim3(N_NODES/64, 1, 3), 128>>>(node_feats + 64, 256, 3, 1, Wupv, Wupv, 64,
                                                        pV, 192, 1, 64, 64, a8, 0, 0, 0);

    // counting sort of edges by receiver (hist fused with density)
    k_zero   <<<N_NODES/256, 256>>>();
    k_hist   <<<N_EDGES/256, 256>>>(edge_index, edge_feats, densw);
    k_scan   <<<1, 1024>>>();
    k_scatter<<<N_EDGES/256, 256>>>(edge_index);

    // per-node tensor-product combine + segment reduction (+ g_AI)
    k_mm<<<N_NODES, 64>>>(edge_attrs, magattr, edge_index, node_attrs);

    // lin_s / lin_v (RB=64)
    gemmk<64,32,false><<<dim3(N_NODES/64, 1, 1), 128>>>(pMS, 320, 1, 0, lins, lins, 64,
                                                        pMSP, 64, 1, 0, 320, a320, 0, 0, 0);
    gemmk<64,32,false><<<dim3(N_NODES/64, 1, 3), 128>>>(pMV, 1536, 1, 512, linv, linv, 64,
                                                        pMVP, 192, 1, 64, 512, a512, 0, 0, 0);

    // skip einsum: coefficients built on the fly in A-staging (RB=64 -> 512 blocks)
    gemmk<64,32,true><<<dim3(N_NODES/64, 1, 4), 128>>>(0, 0, 0, 0, skips, skipv, 64,
                                                       out, 256, 4, 1, 640, a640, 0, pMSP, pMVP);
}

// round 7
// speedup vs baseline: 1.2188x; 1.0000x over previous
#include <cuda_runtime.h>
#include <math.h>

#define N_NODES 8192
#define N_EDGES 65536

typedef unsigned long long ull;

// ---------------- scratch (static device globals; no runtime alloc) ----------------
__device__ float g_S   [N_NODES*64];
__device__ float g_V   [N_NODES*192];
__device__ float g_EDN [N_EDGES];
__device__ float g_TP  [(size_t)N_EDGES*320];
__device__ float g_WM  [(size_t)N_EDGES*832];
__device__ float g_MS  [N_NODES*320];
__device__ float g_MV  [N_NODES*1536];
__device__ float g_AI  [N_NODES*10];          // attrs / (dens+1)
__device__ float g_MSP [N_NODES*64];
__device__ float g_MVP [N_NODES*192];
__device__ int   g_CNT [N_NODES];
__device__ int   g_CUR [N_NODES];
__device__ int   g_OFF [N_NODES+1];
__device__ int   g_SORT[N_EDGES];

__device__ __forceinline__ ull bcast(float f) {
    unsigned int u = __float_as_uint(f);
    ull r;
    asm("mov.b64 %0, {%1, %1};" : "=l"(r) : "r"(u));
    return r;
}
__device__ __forceinline__ ull pack2(float a, float b) {
    return ((ull)__float_as_uint(b) << 32) | __float_as_uint(a);
}
__device__ __forceinline__ void fma2(ull& acc, ull a, ull b) {
    asm("fma.rn.f32x2 %0, %1, %2, %0;" : "+l"(acc) : "l"(a), "l"(b));
}
__device__ __forceinline__ float lo2(ull v) { return __uint_as_float((unsigned int)v); }
__device__ __forceinline__ float hi2(ull v) { return __uint_as_float((unsigned int)(v >> 32)); }
__device__ __forceinline__ float silu(float v) { return v / (1.f + __expf(-v)); }

// ================= fused edge-path kernel =================
// 128 edges per block, 128 threads. Activations live in smem in [k][row]
// (A-tile) layout; each layer output is directly the next layer's A operand.
// Microkernel identical to gemmk: 8 rows x 8 cols per thread, f32x2 FMA.
#define LDH 132
#define SM_MLP ((2*64*LDH + 64*68) * 4)   // hA + hB + Bs = 85 KB

__device__ __forceinline__ void stage_B(float* Bs, const float* __restrict__ src,
                                        int srcStride, int rows, int tid)
{
    for (int j = 0; j < rows / 8; j++) {
        int kk = (tid >> 4) + j * 8;
        int c  = (tid & 15) * 4;
        *(float4*)(Bs + kk * 68 + c) = *(const float4*)(src + (size_t)kk * srcStride + c);
    }
}

template<int K>
__device__ __forceinline__ void tile_mm(const float* hsrc, const float* Bs,
                                        ull* acc, int tx, int ty)
{
#pragma unroll
    for (int i = 0; i < 32; i++) acc[i] = 0ull;
#pragma unroll 4
    for (int kk = 0; kk < K; kk++) {
        const ulonglong2* ap = (const ulonglong2*)(hsrc + kk * LDH + ty * 8);
        ulonglong2 aA = ap[0];
        ulonglong2 aB = ap[1];
        const float4* bp = (const float4*)(Bs + kk * 68 + tx * 8);
        float4 b0 = bp[0], b1 = bp[1];
        ull bb[8];
        bb[0] = bcast(b0.x); bb[1] = bcast(b0.y);
        bb[2] = bcast(b0.z); bb[3] = bcast(b0.w);
        bb[4] = bcast(b1.x); bb[5] = bcast(b1.y);
        bb[6] = bcast(b1.z); bb[7] = bcast(b1.w);
#pragma unroll
        for (int c = 0; c < 8; c++) {
            fma2(acc[c],      aA.x, bb[c]);
            fma2(acc[8 + c],  aA.y, bb[c]);
            fma2(acc[16 + c], aB.x, bb[c]);
            fma2(acc[24 + c], aB.y, bb[c]);
        }
    }
}

// write 8x8 thread tile to global rows (edge-major, row stride rs)
__device__ __forceinline__ void write_gmem(float* dst, int rs, const ull* acc,
                                           float alpha, int tx, int ty)
{
#pragma unroll
    for (int rp = 0; rp < 4; rp++) {
        int r = ty * 8 + rp * 2;
        float* c0 = dst + (size_t)r * rs + tx * 8;
        float* c1 = c0 + rs;
        float4 l0, l1, h0, h1;
        l0.x = lo2(acc[rp*8+0]) * alpha; h0.x = hi2(acc[rp*8+0]) * alpha;
        l0.y = lo2(acc[rp*8+1]) * alpha; h0.y = hi2(acc[rp*8+1]) * alpha;
        l0.z = lo2(acc[rp*8+2]) * alpha; h0.z = hi2(acc[rp*8+2]) * alpha;
        l0.w = lo2(acc[rp*8+3]) * alpha; h0.w = hi2(acc[rp*8+3]) * alpha;
        l1.x = lo2(acc[rp*8+4]) * alpha; h1.x = hi2(acc[rp*8+4]) * alpha;
        l1.y = lo2(acc[rp*8+5]) * alpha; h1.y = hi2(acc[rp*8+5]) * alpha;
        l1.z = lo2(acc[rp*8+6]) * alpha; h1.z = hi2(acc[rp*8+6]) * alpha;
        l1.w = lo2(acc[rp*8+7]) * alpha; h1.w = hi2(acc[rp*8+7]) * alpha;
        *(float4*)(c0)     = l0;
        *(float4*)(c0 + 4) = l1;
        *(float4*)(c1)     = h0;
        *(float4*)(c1 + 4) = h1;
    }
}

// write 8x8 thread tile to smem h-layout [col][row] with silu(alpha*x)
__device__ __forceinline__ void write_h(float* hdst, const ull* acc,
                                        float alpha, int tx, int ty)
{
#pragma unroll
    for (int rp = 0; rp < 4; rp++) {
        int r = ty * 8 + rp * 2;
#pragma unroll
        for (int c = 0; c < 8; c++) {
            float v0 = silu(lo2(acc[rp*8+c]) * alpha);
            float v1 = silu(hi2(acc[rp*8+c]) * alpha);
            *(ull*)(hdst + (tx * 8 + c) * LDH + r) = pack2(v0, v1);
        }
    }
}

__global__ void __launch_bounds__(128) k_mlp(
    const float* __restrict__ EF, const float* __restrict__ MI,
    const int* __restrict__ EI,
    const float* __restrict__ w0, const float* __restrict__ w1,
    const float* __restrict__ w2, const float* __restrict__ w3,
    const float* __restrict__ magw)
{
    extern __shared__ float sm[];
    float* hA = sm;                    // [64][LDH]
    float* hB = sm + 64 * LDH;         // [64][LDH]
    float* Bs = sm + 2 * 64 * LDH;     // [64][68]

    const int tid = threadIdx.x;
    const int tx = tid & 7, ty = tid >> 3;
    const size_t e0 = (size_t)blockIdx.x * 128;

    // stage efm into hA rows 0..15 (efm = concat(edge_feats, maginv[sender]))
    {
        size_t e = e0 + tid;
        float4 a = *(const float4*)(EF + e * 8);
        float4 b = *(const float4*)(EF + e * 8 + 4);
        int snd = EI[e];
        float4 c = *(const float4*)(MI + (size_t)snd * 8);
        float4 d = *(const float4*)(MI + (size_t)snd * 8 + 4);
        hA[ 0*LDH+tid]=a.x; hA[ 1*LDH+tid]=a.y; hA[ 2*LDH+tid]=a.z; hA[ 3*LDH+tid]=a.w;
        hA[ 4*LDH+tid]=b.x; hA[ 5*LDH+tid]=b.y; hA[ 6*LDH+tid]=b.z; hA[ 7*LDH+tid]=b.w;
        hA[ 8*LDH+tid]=c.x; hA[ 9*LDH+tid]=c.y; hA[10*LDH+tid]=c.z; hA[11*LDH+tid]=c.w;
        hA[12*LDH+tid]=d.x; hA[13*LDH+tid]=d.y; hA[14*LDH+tid]=d.z; hA[15*LDH+tid]=d.w;
    }
    __syncthreads();

    ull acc[32];

    // ---- MLP layer 0: hB = silu(efm @ w0 / 4) ----
    stage_B(Bs, w0, 64, 16, tid);
    __syncthreads();
    tile_mm<16>(hA, Bs, acc, tx, ty);
    write_h(hB, acc, 0.25f, tx, ty);
    __syncthreads();

    // ---- magw projection: WM[e, j*64+c] = efm @ magw / 4 ----
    for (int j = 0; j < 13; j++) {
        stage_B(Bs, magw + j * 64, 832, 16, tid);
        __syncthreads();
        tile_mm<16>(hA, Bs, acc, tx, ty);
        write_gmem(g_WM + e0 * 832 + j * 64, 832, acc, 0.25f, tx, ty);
        __syncthreads();
    }

    // ---- MLP layer 1: hA = silu(hB @ w1 / 8) ----
    stage_B(Bs, w1, 64, 64, tid);
    __syncthreads();
    tile_mm<64>(hB, Bs, acc, tx, ty);
    write_h(hA, acc, 0.125f, tx, ty);
    __syncthreads();

    // ---- MLP layer 2: hB = silu(hA @ w2 / 8) ----
    stage_B(Bs, w2, 64, 64, tid);
    __syncthreads();
    tile_mm<64>(hA, Bs, acc, tx, ty);
    write_h(hB, acc, 0.125f, tx, ty);
    __syncthreads();

    // ---- TP projection: TP[e, j*64+c] = hB @ w3 / 8 ----
    for (int j = 0; j < 5; j++) {
        stage_B(Bs, w3 + j * 64, 320, 64, tid);
        __syncthreads();
        tile_mm<64>(hB, Bs, acc, tx, ty);
        write_gmem(g_TP + e0 * 320 + j * 64, 320, acc, 0.125f, tx, ty);
        __syncthreads();
    }
}

// ================= register-blocked GEMM (node side) =================
template<int RB, int KT, bool SKIP>
__global__ void __launch_bounds__(128) gemmk(
    const float* __restrict__ A, long ars, int acs, long azs,
    const float* __restrict__ B0, const float* __restrict__ Bz, int brs,
    float* __restrict__ C, long crs, int ccs, long czs,
    int K, float alpha, int act,
    const float* __restrict__ MSP, const float* __restrict__ MVP)
{
    const int LDA = RB + 4;
    const int RPT = RB / 16;
    const int PPT = RPT / 2;
    __shared__ float As[KT*(RB+4)];
    __shared__ float Bs[KT*68];

    const int tid = threadIdx.x;
    const int tx = tid & 7;
    const int ty = tid >> 3;
    const long row0 = (long)blockIdx.x * RB;
    const int  col0 = blockIdx.y * 64;
    const int  z = blockIdx.z;
    const float* __restrict__ B = (z == 0) ? B0 : Bz;
    C += (long)z * czs;

    const int arow = tid & (RB - 1);
    const int kseg = (RB == 128) ? 0 : ((tid >> 6) * (KT / 2));
    const int KPT  = (RB == 128) ? KT : KT / 2;

    const float* Arow;
    const float* ai = 0;
    if (SKIP) {
        Arow = (z == 0) ? (MSP + (row0 + arow) * 64)
                        : (MVP + (row0 + arow) * 192 + (z - 1) * 64);
        ai = g_AI + (row0 + arow) * 10;
    } else {
        Arow = A + (long)z * azs + (row0 + arow) * ars;
    }

    ull acc[PPT * 8];
#pragma unroll
    for (int i = 0; i < PPT * 8; i++) acc[i] = 0ull;

    for (int k0 = 0; k0 < K; k0 += KT) {
        if (SKIP) {
#pragma unroll 8
            for (int c = 0; c < KPT; c++) {
                int k = k0 + kseg + c;
                int u = (k * 6554) >> 16;
                int v = k - u * 10;
                As[(kseg + c) * LDA + arow] = Arow[u] * ai[v];
            }
        } else if (acs == 1) {
#pragma unroll
            for (int c = 0; c < KPT / 4; c++) {
                int kk = kseg + c * 4;
                float4 val = make_float4(0.f, 0.f, 0.f, 0.f);
                if (k0 + kk < K)
                    val = *(const float4*)(Arow + k0 + kk);
                As[(kk + 0) * LDA + arow] = val.x;
                As[(kk + 1) * LDA + arow] = val.y;
                As[(kk + 2) * LDA + arow] = val.z;
                As[(kk + 3) * LDA + arow] = val.w;
            }
        } else {
#pragma unroll 8
            for (int c = 0; c < KPT; c++) {
                int kk = kseg + c;
                float v = 0.f;
                if (k0 + kk < K) v = Arow[(long)(k0 + kk) * acs];
                As[kk * LDA + arow] = v;
            }
        }
#pragma unroll
        for (int j = 0; j < KT / 8; j++) {
            int kk = (tid >> 4) + j * 8;
            int c  = (tid & 15) * 4;
            float4 val = make_float4(0.f, 0.f, 0.f, 0.f);
            if (k0 + kk < K)
                val = *(const float4*)(B + (size_t)(k0 + kk) * brs + col0 + c);
            *(float4*)(Bs + kk * 68 + c) = val;
        }
        __syncthreads();

#pragma unroll 4
        for (int kk = 0; kk < KT; kk++) {
            ull ar[PPT];
            {
                const ulonglong2* ap = (const ulonglong2*)(As + kk * LDA + ty * RPT);
                ulonglong2 t0 = ap[0];
                ar[0] = t0.x; ar[1] = t0.y;
                if (RB == 128) {
                    ulonglong2 t1 = ap[1];
                    ar[2] = t1.x; ar[3] = t1.y;
                }
            }
            const float4* bp = (const float4*)(Bs + kk * 68 + tx * 8);
            float4 b0 = bp[0], b1 = bp[1];
            ull bb[8];
            bb[0] = bcast(b0.x); bb[1] = bcast(b0.y);
            bb[2] = bcast(b0.z); bb[3] = bcast(b0.w);
            bb[4] = bcast(b1.x); bb[5] = bcast(b1.y);
            bb[6] = bcast(b1.z); bb[7] = bcast(b1.w);
#pragma unroll
            for (int c = 0; c < 8; c++)
#pragma unroll
                for (int p = 0; p < PPT; p++)
                    fma2(acc[p * 8 + c], ar[p], bb[c]);
        }
        __syncthreads();
    }

#pragma unroll
    for (int rp = 0; rp < PPT; rp++) {
        long r = row0 + ty * RPT + rp * 2;
        float lo[8], hi[8];
#pragma unroll
        for (int c = 0; c < 8; c++) {
            ull av = acc[rp * 8 + c];
            float v0 = lo2(av) * alpha;
            float v1 = hi2(av) * alpha;
            if (act) { v0 = silu(v0); v1 = silu(v1); }
            lo[c] = v0; hi[c] = v1;
        }
        if (ccs == 1) {
            float* c0 = C + r * crs + col0 + tx * 8;
            float* c1 = c0 + crs;
            *(float4*)(c0)     = make_float4(lo[0], lo[1], lo[2], lo[3]);
            *(float4*)(c0 + 4) = make_float4(lo[4], lo[5], lo[6], lo[7]);
            *(float4*)(c1)     = make_float4(hi[0], hi[1], hi[2], hi[3]);
            *(float4*)(c1 + 4) = make_float4(hi[4], hi[5], hi[6], hi[7]);
        } else {
#pragma unroll
            for (int c = 0; c < 8; c++) {
                long col = (long)(col0 + tx * 8 + c) * ccs;
                C[r * crs + col] = lo[c];
                C[(r + 1) * crs + col] = hi[c];
            }
        }
    }
}

// ---------------- counting sort by receiver (hist fused with density) ----------------
__global__ void k_zero()
{
    int i = blockIdx.x * 256 + threadIdx.x;
    if (i < N_NODES) { g_CNT[i] = 0; g_CUR[i] = 0; }
}
__global__ void k_hist(const int* __restrict__ EI, const float* __restrict__ EF,
                       const float* __restrict__ DW)
{
    int e = blockIdx.x * 256 + threadIdx.x;
    atomicAdd(&g_CNT[EI[N_EDGES + e]], 1);
    float d = 0.f;
#pragma unroll
    for (int i = 0; i < 8; i++) d += EF[e * 8 + i] * DW[i];
    d *= 0.3535533905932738f;                     // 1/sqrt(8)
    g_EDN[e] = tanhf(d * d);
}
__global__ void k_scan()
{
    __shared__ int part[1024];
    int t = threadIdx.x;
    int loc[8]; int s = 0;
#pragma unroll
    for (int j = 0; j < 8; j++) { loc[j] = s; s += g_CNT[t * 8 + j]; }
    part[t] = s;
    __syncthreads();
    for (int off = 1; off < 1024; off <<= 1) {
        int v = (t >= off) ? part[t - off] : 0;
        __syncthreads();
        part[t] += v;
        __syncthreads();
    }
    int excl = part[t] - s;
#pragma unroll
    for (int j = 0; j < 8; j++) g_OFF[t * 8 + j] = excl + loc[j];
    if (t == 1023) g_OFF[N_NODES] = part[1023];
}
__global__ void k_scatter(const int* __restrict__ EI)
{
    int e = blockIdx.x * 256 + threadIdx.x;
    int r = EI[N_EDGES + e];
    int p = g_OFF[r] + atomicAdd(&g_CUR[r], 1);
    g_SORT[p] = e;
}

// ---------------- per-node edge combine + segment reduction (no atomics) ----------------
__global__ void __launch_bounds__(64) k_mm(const float* __restrict__ EA,
                                           const float* __restrict__ MA,
                                           const int* __restrict__ EI,
                                           const float* __restrict__ ATTR)
{
    const int n = blockIdx.x;
    const int u = threadIdx.x;
    const int beg = g_OFF[n], end = g_OFF[n + 1];

    float as0 = 0, as1 = 0, as2 = 0, as3 = 0, as4 = 0;
    float av[8][3];
#pragma unroll
    for (int j = 0; j < 8; j++)
#pragma unroll
        for (int i = 0; i < 3; i++) av[j][i] = 0.f;
    float dens = 0.f;

    const float I3 = 0.5773502691896258f;   // 1/sqrt(3)
    const float I2 = 0.7071067811865476f;   // 1/sqrt(2)

    int e_nx = 0, s_nx = 0;
    if (beg < end) { e_nx = g_SORT[beg]; s_nx = EI[e_nx]; }

    for (int q = beg; q < end; q++) {
        const int e = e_nx, snd = s_nx;
        if (q + 1 < end) { e_nx = g_SORT[q + 1]; s_nx = EI[e_nx]; }

        const float4 eav = *(const float4*)(EA + (size_t)e * 4);
        const float y0 = eav.x, yx = eav.y, yy = eav.z, yz = eav.w;
        const float4 mav = *(const float4*)(MA + (size_t)snd * 4);
        const float m0 = mav.x, mx = mav.y, my = mav.z, mz = mav.w;
        const float xs = g_S[(size_t)snd * 64 + u];
        const float* vp = g_V + (size_t)snd * 192 + u;
        const float vx = vp[0], vy = vp[64], vz = vp[128];
        const float* tp = g_TP + (size_t)e * 320 + u;
        const float t0 = tp[0], t1 = tp[64], t2 = tp[128], t3 = tp[192], t4 = tp[256];
        const float* wm = g_WM + (size_t)e * 832 + u;

        const float ms0 = t0 * xs * y0;
        const float A0x = t1 * xs * yx, A0y = t1 * xs * yy, A0z = t1 * xs * yz;
        const float B0x = t2 * vx * y0, B0y = t2 * vy * y0, B0z = t2 * vz * y0;
        const float ms1 = t3 * (vx * yx + vy * yy + vz * yz) * I3;
        const float cx = vy * yz - vz * yy;
        const float cy = vz * yx - vx * yz;
        const float cz = vx * yy - vy * yx;
        const float C0x = t4 * cx * I2, C0y = t4 * cy * I2, C0z = t4 * cz * I2;

        as0 += wm[0] * ms0 * m0;
        { float w_ = wm[64] * ms0;  av[0][0] += w_ * mx; av[0][1] += w_ * my; av[0][2] += w_ * mz; }
        as1 += wm[128] * ms1 * m0;
        { float w_ = wm[192] * ms1; av[1][0] += w_ * mx; av[1][1] += w_ * my; av[1][2] += w_ * mz; }

        { float w_ = wm[256] * m0;  av[2][0] += w_ * A0x; av[2][1] += w_ * A0y; av[2][2] += w_ * A0z; }
        as2 += wm[320] * (A0x * mx + A0y * my + A0z * mz) * I3;
        { float w_ = wm[384] * I2;
          av[3][0] += w_ * (A0y * mz - A0z * my);
          av[3][1] += w_ * (A0z * mx - A0x * mz);
          av[3][2] += w_ * (A0x * my - A0y * mx); }

        { float w_ = wm[448] * m0;  av[4][0] += w_ * B0x; av[4][1] += w_ * B0y; av[4][2] += w_ * B0z; }
        as3 += wm[512] * (B0x * mx + B0y * my + B0z * mz) * I3;
        { float w_ = wm[576] * I2;
          av[5][0] += w_ * (B0y * mz - B0z * my);
          av[5][1] += w_ * (B0z * mx - B0x * mz);
          av[5][2] += w_ * (B0x * my - B0y * mx); }

        { float w_ = wm[640] * m0;  av[6][0] += w_ * C0x; av[6][1] += w_ * C0y; av[6][2] += w_ * C0z; }
        as4 += wm[704] * (C0x * mx + C0y * my + C0z * mz) * I3;
        { float w_ = wm[768] * I2;
          av[7][0] += w_ * (C0y * mz - C0z * my);
          av[7][1] += w_ * (C0z * mx - C0x * mz);
          av[7][2] += w_ * (C0x * my - C0y * mx); }

        dens += g_EDN[e];
    }

    const size_t b = (size_t)n * 320 + u;
    g_MS[b]       = as0;
    g_MS[b + 64]  = as1;
    g_MS[b + 128] = as2;
    g_MS[b + 192] = as3;
    g_MS[b + 256] = as4;
    const size_t bv = (size_t)n * 1536 + u;
#pragma unroll
    for (int i = 0; i < 3; i++)
#pragma unroll
        for (int j = 0; j < 8; j++)
            g_MV[bv + i * 512 + j * 64] = av[j][i];
    if (u < 10) g_AI[n * 10 + u] = ATTR[n * 10 + u] / (dens + 1.f);
}

// ---------------- launcher ----------------
extern "C" void kernel_launch(void* const* d_in, const int* in_sizes, int n_in,
                              void* d_out, int out_size)
{
    (void)in_sizes; (void)n_in; (void)out_size;
    const float* node_attrs = (const float*)d_in[0];
    const float* node_feats = (const float*)d_in[1];
    const float* edge_attrs = (const float*)d_in[2];
    const float* edge_feats = (const float*)d_in[3];
    const int*   edge_index = (const int*)  d_in[4];
    const float* maginv     = (const float*)d_in[5];
    const float* magattr    = (const float*)d_in[6];
    const float* Wups       = (const float*)d_in[7];
    const float* Wupv       = (const float*)d_in[8];
    const float* w0         = (const float*)d_in[9];
    const float* w1         = (const float*)d_in[10];
    const float* w2         = (const float*)d_in[11];
    const float* w3         = (const float*)d_in[12];
    const float* magw       = (const float*)d_in[13];
    const float* densw      = (const float*)d_in[14];
    const float* lins       = (const float*)d_in[15];
    const float* linv       = (const float*)d_in[16];
    const float* skips      = (const float*)d_in[17];
    const float* skipv      = (const float*)d_in[18];
    float* out = (float*)d_out;

    float *pS, *pV, *pMS, *pMV, *pMSP, *pMVP;
    cudaGetSymbolAddress((void**)&pS,   g_S);
    cudaGetSymbolAddress((void**)&pV,   g_V);
    cudaGetSymbolAddress((void**)&pMS,  g_MS);
    cudaGetSymbolAddress((void**)&pMV,  g_MV);
    cudaGetSymbolAddress((void**)&pMSP, g_MSP);
    cudaGetSymbolAddress((void**)&pMVP, g_MVP);

    cudaFuncSetAttribute(k_mlp, cudaFuncAttributeMaxDynamicSharedMemorySize, SM_MLP);

    const float a8   = 0.125f;
    const float a320 = 1.f / sqrtf(320.f);
    const float a512 = 1.f / sqrtf(512.f);
    const float a640 = 1.f / sqrtf(640.f);

    // sort bookkeeping first so k_mlp lands in profile slot 3
    k_zero   <<<N_NODES/256, 256>>>();                                   // 0
    k_hist   <<<N_EDGES/256, 256>>>(edge_index, edge_feats, densw);      // 1
    k_scan   <<<1, 1024>>>();                                            // 2

    // fused edge path: efm + MLP + WM + TP in one kernel                // 3 (profiled)
    k_mlp<<<N_EDGES/128, 128, SM_MLP>>>(edge_feats, maginv, edge_index,
                                        w0, w1, w2, w3, magw);

    k_scatter<<<N_EDGES/256, 256>>>(edge_index);                         // 4

    // node up-projection
    gemmk<64,32,false><<<dim3(N_NODES/64, 1, 1), 128>>>(node_feats, 256, 1, 0, Wups, Wups, 64,
                                                        pS, 64, 1, 0, 64, a8, 0, 0, 0);
    gemmk<64,32,false><<<dim3(N_NODES/64, 1, 3), 128>>>(node_feats + 64, 256, 3, 1, Wupv, Wupv, 64,
                                                        pV, 192, 1, 64, 64, a8, 0, 0, 0);

    // per-node tensor-product combine + segment reduction (+ g_AI)
    k_mm<<<N_NODES, 64>>>(edge_attrs, magattr, edge_index, node_attrs);

    // lin_s / lin_v
    gemmk<64,32,false><<<dim3(N_NODES/64, 1, 1), 128>>>(pMS, 320, 1, 0, lins, lins, 64,
                                                        pMSP, 64, 1, 0, 320, a320, 0, 0, 0);
    gemmk<64,32,false><<<dim3(N_NODES/64, 1, 3), 128>>>(pMV, 1536, 1, 512, linv, linv, 64,
                                                        pMVP, 192, 1, 64, 512, a512, 0, 0, 0);

    // skip einsum: coefficients built on the fly in A-staging
    gemmk<64,32,true><<<dim3(N_NODES/64, 1, 4), 128>>>(0, 0, 0, 0, skips, skipv, 64,
                                                       out, 256, 4, 1, 640, a640, 0, pMSP, pMVP);
}